// round 6
// baseline (speedup 1.0000x reference)
#include <cuda_runtime.h>

#define EPSF     1.1920928955078125e-07f
#define LOG2E    1.4426950408889634f
#define NSAMP    2000
#define NPAD     2048
#define Y0F      0.9999f
#define NROWS    65536
#define MAGICF   12582912.0f     // 1.5 * 2^23

#define NCH      16      // chunks per row
#define CPTS     128     // points per chunk
#define CF4      64      // float4 per chunk
#define CF4P     65      // padded (bank skew for lane-varying rewalk)
#define TPB      64      // threads (rows) per block
#define NBLK     (NROWS / TPB)

// Chunked padded table: g_tabC[c*CF4P + q] = (ax_{2i}, ax_{2i+1}, l2_{2i}, l2_{2i+1})
__device__ float4 g_tabC[NCH * CF4P];
__device__ float  g_grid[NPAD];

typedef unsigned long long u64;
typedef unsigned int u32;

__device__ __forceinline__ float ex2(float x) {
    float r;
    asm("ex2.approx.ftz.f32 %0, %1;" : "=f"(r) : "f"(x));
    return r;
}
__device__ __forceinline__ u64 pk(float a, float b) {
    u64 r;
    asm("mov.b64 %0, {%1, %2};" : "=l"(r) : "f"(a), "f"(b));
    return r;
}
__device__ __forceinline__ void upk(float& a, float& b, u64 r) {
    asm("mov.b64 {%0, %1}, %2;" : "=f"(a), "=f"(b) : "l"(r));
}
#define ADD2(d,a,b) asm("add.rn.f32x2 %0, %1, %2;"     : "=l"(d) : "l"(a), "l"(b))
#define SUB2(d,a,b) asm("sub.rn.f32x2 %0, %1, %2;"     : "=l"(d) : "l"(a), "l"(b))
#define MUL2(d,a,b) asm("mul.rn.f32x2 %0, %1, %2;"     : "=l"(d) : "l"(a), "l"(b))
#define FMA2(d,a,b,c) asm("fma.rn.f32x2 %0, %1, %2, %3;" : "=l"(d) : "l"(a), "l"(b), "l"(c))

__global__ void init_tables_kernel() {
    int i = blockIdx.x * blockDim.x + threadIdx.x;  // 0..2047
    if (i >= NPAD) return;
    const float step = 2.0f * Y0F / 1999.0f;
    float ax, l2, g;
    if (i < NSAMP) {
        float x = (i == NSAMP - 1) ? Y0F
                                   : __fadd_rn(__fmul_rn((float)i, step), -Y0F);
        ax = 0.5f * logf((1.0f + x) / (1.0f - x) + EPSF);
        l2 = -log2f(1.0f - x * x);   // log2(1/(1-x^2))
        g  = x;
    } else {
        ax = 0.0f; l2 = -1e30f; g = Y0F;   // padding inert
    }
    g_grid[i] = g;
    int c = i >> 7, q = (i & 127) >> 1, h = i & 1;
    float* f = (float*)&g_tabC[c * CF4P + q];
    f[h]     = ax;
    f[2 + h] = l2;
}

// thread = row. 64 rows/block so all 1024 CTAs are co-resident (1 wave).
__global__ __launch_bounds__(TPB) void sample_kernel(
    const float* __restrict__ mean,
    const float* __restrict__ stdv,
    const float* __restrict__ uni,
    float* __restrict__ out)
{
    __shared__ float4 tab[NCH * CF4P];   // 16640 B
    __shared__ float  chs[NCH * TPB];    // 4096 B

    const int tid = threadIdx.x;
    for (int i = tid; i < NCH * CF4P; i += TPB) tab[i] = g_tabC[i];
    __syncthreads();

    const int row = blockIdx.x * TPB + tid;

    const float mu = __ldg(mean + row);
    const float sg = __ldg(stdv + row) + EPSF;
    const float u  = __ldg(uni + row);
    const float k2 = (-0.5f * LOG2E) / (sg * sg);

    const u64 nmu   = pk(-mu, -mu);
    const u64 k2p   = pk(k2, k2);
    // packed constants for poly exp2 (deg-5 Taylor of 2^f, |f|<=0.5, err<=2.4e-6)
    const u64 magicP = pk(MAGICF, MAGICF);
    const u64 c5p = pk(1.3333558e-3f, 1.3333558e-3f);
    const u64 c4p = pk(9.6181291e-3f, 9.6181291e-3f);
    const u64 c3p = pk(5.5504109e-2f, 5.5504109e-2f);
    const u64 c2p = pk(2.4022651e-1f, 2.4022651e-1f);
    const u64 c1p = pk(6.9314718e-1f, 6.9314718e-1f);
    const u64 c0p = pk(1.0f, 1.0f);

    // ---- Phase 1: chunk sums; hybrid MUFU/poly exp to balance pipes ----
    float S = 0.0f;
    for (int k = 0; k < NCH; ++k) {
        const float4* cp = tab + k * CF4P;
        float s0 = 0.0f, s1 = 0.0f;
        u64 sp = pk(0.0f, 0.0f);
        #pragma unroll 16
        for (int j = 0; j < CF4; ++j) {
            float4 v = cp[j];  // broadcast LDS.128
            u64 axp = pk(v.x, v.y);
            u64 l2p = pk(v.z, v.w);
            u64 t, tt, arg;
            ADD2(t, axp, nmu);
            MUL2(tt, t, t);
            FMA2(arg, tt, k2p, l2p);
            if ((j & 15) < 3) {
                // ---- packed polynomial exp2 on the fma pipe (beta = 3/16) ----
                // lower clamp per-half on the alu pipe (FMNMX); arg <= ~12.3 always
                float alo, ahi;
                upk(alo, ahi, arg);
                alo = fmaxf(alo, -120.0f);
                ahi = fmaxf(ahi, -120.0f);
                arg = pk(alo, ahi);
                u64 m, iv, f, p;
                ADD2(m, arg, magicP);    // round-to-nearest int in mantissa
                SUB2(iv, m, magicP);     // iv = (float)i
                SUB2(f, arg, iv);        // f in [-0.5, 0.5]
                FMA2(p, c5p, f, c4p);
                FMA2(p, p,  f, c3p);
                FMA2(p, p,  f, c2p);
                FMA2(p, p,  f, c1p);
                FMA2(p, p,  f, c0p);
                // scale by 2^i: add (i << 23) to float bits, per half
                u32 mlo = (u32)m,        mhi = (u32)(m >> 32);
                u32 plo = (u32)p,        phi = (u32)(p >> 32);
                float rlo = __uint_as_float(plo + (mlo << 23));
                float rhi = __uint_as_float(phi + (mhi << 23));
                u64 r = pk(rlo, rhi);
                ADD2(sp, sp, r);
            } else {
                float lo, hi;
                upk(lo, hi, arg);
                s0 += ex2(lo);
                s1 += ex2(hi);
            }
        }
        float splo, sphi;
        upk(splo, sphi, sp);
        float cs = (s0 + s1) + (splo + sphi);
        chs[k * TPB + tid] = cs;
        S += cs;
    }

    const float invnorm = rsqrtf(6.283185307179586f * sg * sg);
    const float denom   = __fmaf_rn(invnorm, S, EPSF);   // S_norm + EPS
    const float Traw    = u * denom / invnorm;           // threshold, raw space

    // ---- Phase 2a: locate crossing chunk ----
    float cum = 0.0f, base = 0.0f;
    int kc = -1;
    #pragma unroll
    for (int k = 0; k < NCH; ++k) {
        float cs = chs[k * TPB + tid];
        float ni = cum + cs;
        if (kc < 0 && ni > Traw) { kc = k; base = cum; }
        cum = ni;
    }

    int idx;
    if (kc < 0) {
        float Snorm = invnorm * S;
        float cl = Snorm / (Snorm + EPSF);   // reference's cdf[last]
        idx = (u < cl) ? (NSAMP - 1) : 0;
    } else {
        // ---- Phase 2b: sequential rewalk of the crossing chunk (exact ex2) ----
        const float T2 = Traw - base;
        const float4* cp = tab + kc * CF4P;
        float c = 0.0f;
        idx = -1;
        #pragma unroll 8
        for (int j = 0; j < CF4; ++j) {
            float4 v = cp[j];
            float t0 = v.x - mu;
            float p0 = ex2(__fmaf_rn(t0 * t0, k2, v.z));
            c += p0;
            if (idx < 0 && c > T2) idx = kc * CPTS + 2 * j;
            float t1 = v.y - mu;
            float p1 = ex2(__fmaf_rn(t1 * t1, k2, v.w));
            c += p1;
            if (idx < 0 && c > T2) idx = kc * CPTS + 2 * j + 1;
        }
        if (idx < 0) idx = kc * CPTS + CPTS - 1;
        if (idx > NSAMP - 1) idx = NSAMP - 1;
    }

    // ---- Recompute prob at final index (exact ex2) ----
    {
        int c2 = idx >> 7, q = (idx & 127) >> 1, h = idx & 1;
        float4 v = tab[c2 * CF4P + q];
        float ax = h ? v.y : v.x;
        float l2 = h ? v.w : v.z;
        float t = ax - mu;
        float p = ex2(__fmaf_rn(t * t, k2, l2));
        float prob = invnorm * p / denom;

        out[row]         = __ldg(g_grid + idx);  // sampled_values
        out[NROWS + row] = prob;                 // sampled_probs
    }
}

extern "C" void kernel_launch(void* const* d_in, const int* in_sizes, int n_in,
                              void* d_out, int out_size) {
    const float* mean = (const float*)d_in[0];
    const float* stdv = (const float*)d_in[1];
    const float* uni  = (const float*)d_in[2];
    float* out = (float*)d_out;

    init_tables_kernel<<<2, 1024>>>();
    sample_kernel<<<NBLK, TPB>>>(mean, stdv, uni, out);
}

// round 7
// speedup vs baseline: 1.0846x; 1.0846x over previous
#include <cuda_runtime.h>

#define EPSF     1.1920928955078125e-07f
#define LOG2E    1.4426950408889634f
#define NSAMP    2000
#define NPAD     2048
#define Y0F      0.9999f
#define NROWS    65536
#define MAGICF   12582912.0f     // 1.5 * 2^23
#define FULLMASK 0xffffffffu

#define NCH      16      // chunks per row
#define CPT      8       // chunks per thread (2 threads/row)
#define CPTS     128     // points per chunk
#define CF4      64      // float4 per chunk
#define CF4P     65      // padded (bank skew for lane-varying rewalk)
#define TPB      128
#define NBLK     (NROWS * 2 / TPB)   // 1024

__device__ float4 g_tabC[NCH * CF4P];
__device__ float  g_grid[NPAD];

typedef unsigned long long u64;
typedef unsigned int u32;

__device__ __forceinline__ float ex2(float x) {
    float r;
    asm("ex2.approx.ftz.f32 %0, %1;" : "=f"(r) : "f"(x));
    return r;
}
__device__ __forceinline__ u64 pk(float a, float b) {
    u64 r;
    asm("mov.b64 %0, {%1, %2};" : "=l"(r) : "f"(a), "f"(b));
    return r;
}
__device__ __forceinline__ void upk(float& a, float& b, u64 r) {
    asm("mov.b64 {%0, %1}, %2;" : "=f"(a), "=f"(b) : "l"(r));
}
#define ADD2(d,a,b) asm("add.rn.f32x2 %0, %1, %2;"     : "=l"(d) : "l"(a), "l"(b))
#define SUB2(d,a,b) asm("sub.rn.f32x2 %0, %1, %2;"     : "=l"(d) : "l"(a), "l"(b))
#define MUL2(d,a,b) asm("mul.rn.f32x2 %0, %1, %2;"     : "=l"(d) : "l"(a), "l"(b))
#define FMA2(d,a,b,c) asm("fma.rn.f32x2 %0, %1, %2, %3;" : "=l"(d) : "l"(a), "l"(b), "l"(c))

__global__ void init_tables_kernel() {
    int i = blockIdx.x * blockDim.x + threadIdx.x;  // 0..2047
    if (i >= NPAD) return;
    const float step = 2.0f * Y0F / 1999.0f;
    float ax, l2, g;
    if (i < NSAMP) {
        float x = (i == NSAMP - 1) ? Y0F
                                   : __fadd_rn(__fmul_rn((float)i, step), -Y0F);
        ax = 0.5f * logf((1.0f + x) / (1.0f - x) + EPSF);
        l2 = -log2f(1.0f - x * x);
        g  = x;
    } else {
        ax = 0.0f; l2 = -1e30f; g = Y0F;   // padding inert
    }
    g_grid[i] = g;
    int c = i >> 7, q = (i & 127) >> 1, h = i & 1;
    float* f = (float*)&g_tabC[c * CF4P + q];
    f[h]     = ax;
    f[2 + h] = l2;
}

// 2 threads per row: thread half h owns chunks [8h, 8h+8).
__global__ __launch_bounds__(TPB) void sample_kernel(
    const float* __restrict__ mean,
    const float* __restrict__ stdv,
    const float* __restrict__ uni,
    float* __restrict__ out)
{
    __shared__ float4 tab[NCH * CF4P];   // 16640 B

    const int tid  = threadIdx.x;
    for (int i = tid; i < NCH * CF4P; i += TPB) tab[i] = g_tabC[i];
    __syncthreads();

    const int gt   = blockIdx.x * TPB + tid;
    const int row  = gt >> 1;
    const int half = gt & 1;
    const int lane = tid & 31;

    const float mu = __ldg(mean + row);
    const float sg = __ldg(stdv + row) + EPSF;
    const float u  = __ldg(uni + row);
    const float k2 = (-0.5f * LOG2E) / (sg * sg);

    const u64 nmu   = pk(-mu, -mu);
    const u64 k2p   = pk(k2, k2);
    const u64 magicP = pk(MAGICF, MAGICF);
    const u64 c5p = pk(1.3333558e-3f, 1.3333558e-3f);
    const u64 c4p = pk(9.6181291e-3f, 9.6181291e-3f);
    const u64 c3p = pk(5.5504109e-2f, 5.5504109e-2f);
    const u64 c2p = pk(2.4022651e-1f, 2.4022651e-1f);
    const u64 c1p = pk(6.9314718e-1f, 6.9314718e-1f);
    const u64 c0p = pk(1.0f, 1.0f);

    // ---- Phase 1: my 8 chunk sums (registers); hybrid MUFU/poly exp ----
    float cs[CPT];
    float ps = 0.0f;
    #pragma unroll
    for (int c = 0; c < CPT; ++c) {
        const float4* cp = tab + (half * CPT + c) * CF4P;
        float s0 = 0.0f, s1 = 0.0f;
        u64 sp = pk(0.0f, 0.0f);
        #pragma unroll 16
        for (int j = 0; j < CF4; ++j) {
            float4 v = cp[j];  // broadcast LDS.128
            u64 axp = pk(v.x, v.y);
            u64 l2p = pk(v.z, v.w);
            u64 t, tt, arg;
            ADD2(t, axp, nmu);
            MUL2(tt, t, t);
            FMA2(arg, tt, k2p, l2p);
            if ((j & 15) < 3) {
                // packed poly exp2 on fma pipe (beta = 3/16); clamp on alu pipe
                float alo, ahi;
                upk(alo, ahi, arg);
                alo = fmaxf(alo, -120.0f);
                ahi = fmaxf(ahi, -120.0f);
                arg = pk(alo, ahi);
                u64 m, iv, f, p;
                ADD2(m, arg, magicP);
                SUB2(iv, m, magicP);
                SUB2(f, arg, iv);
                FMA2(p, c5p, f, c4p);
                FMA2(p, p,  f, c3p);
                FMA2(p, p,  f, c2p);
                FMA2(p, p,  f, c1p);
                FMA2(p, p,  f, c0p);
                u32 mlo = (u32)m, mhi = (u32)(m >> 32);
                u32 plo = (u32)p, phi = (u32)(p >> 32);
                float rlo = __uint_as_float(plo + (mlo << 23));
                float rhi = __uint_as_float(phi + (mhi << 23));
                u64 r = pk(rlo, rhi);
                ADD2(sp, sp, r);
            } else {
                float lo, hi;
                upk(lo, hi, arg);
                s0 += ex2(lo);
                s1 += ex2(hi);
            }
        }
        float splo, sphi;
        upk(splo, sphi, sp);
        float v = (s0 + s1) + (splo + sphi);
        cs[c] = v;
        ps += v;        // same order as the cum walk below -> bit-consistent
    }

    // ---- Pair handoff: excl (exact boundary) and shared S ----
    float pso = __shfl_xor_sync(FULLMASK, ps, 1);     // partner's ps
    float excl = half ? pso : 0.0f;
    float cum = excl;
    #pragma unroll
    for (int c = 0; c < CPT; ++c) cum += cs[c];
    // S = half1's final cum == exact sequential full sum; broadcast to both
    float S = __shfl_sync(FULLMASK, cum, lane | 1);

    const float invnorm = rsqrtf(6.283185307179586f * sg * sg);
    const float denom   = __fmaf_rn(invnorm, S, EPSF);
    const float Traw    = u * denom / invnorm;

    // ---- Phase 2a: crossing chunk within my half ----
    int kc = -1;
    float base = 0.0f;
    float c2w = excl;
    #pragma unroll
    for (int c = 0; c < CPT; ++c) {
        float ni = c2w + cs[c];
        if (kc < 0 && ni > Traw) { kc = half * CPT + c; base = c2w; }
        c2w = ni;
    }
    if (excl > Traw) kc = -1;   // partner already crossed

    unsigned bal = __ballot_sync(FULLMASK, kc >= 0);
    bool pair_none = (((bal >> (lane & ~1)) & 3u) == 0u);
    bool am_writer = (kc >= 0) || (pair_none && half == 1);

    if (am_writer) {
        int idx;
        if (kc < 0) {
            float Snorm = invnorm * S;
            float cl = Snorm / (Snorm + EPSF);   // reference's cdf[last]
            idx = (u < cl) ? (NSAMP - 1) : 0;
        } else {
            // ---- Phase 2b: rewalk crossing chunk (exact ex2) ----
            const float T2 = Traw - base;
            const float4* cp = tab + kc * CF4P;
            float c = 0.0f;
            idx = -1;
            #pragma unroll 8
            for (int j = 0; j < CF4; ++j) {
                float4 v = cp[j];
                float t0 = v.x - mu;
                float p0 = ex2(__fmaf_rn(t0 * t0, k2, v.z));
                c += p0;
                if (idx < 0 && c > T2) idx = kc * CPTS + 2 * j;
                float t1 = v.y - mu;
                float p1 = ex2(__fmaf_rn(t1 * t1, k2, v.w));
                c += p1;
                if (idx < 0 && c > T2) idx = kc * CPTS + 2 * j + 1;
            }
            if (idx < 0) idx = kc * CPTS + CPTS - 1;
            if (idx > NSAMP - 1) idx = NSAMP - 1;
        }

        // ---- Recompute prob at final index (exact ex2) ----
        int cc = idx >> 7, q = (idx & 127) >> 1, h = idx & 1;
        float4 v = tab[cc * CF4P + q];
        float ax = h ? v.y : v.x;
        float l2 = h ? v.w : v.z;
        float t = ax - mu;
        float p = ex2(__fmaf_rn(t * t, k2, l2));
        float prob = invnorm * p / denom;

        out[row]         = __ldg(g_grid + idx);
        out[NROWS + row] = prob;
    }
}

extern "C" void kernel_launch(void* const* d_in, const int* in_sizes, int n_in,
                              void* d_out, int out_size) {
    const float* mean = (const float*)d_in[0];
    const float* stdv = (const float*)d_in[1];
    const float* uni  = (const float*)d_in[2];
    float* out = (float*)d_out;

    init_tables_kernel<<<2, 1024>>>();
    sample_kernel<<<NBLK, TPB>>>(mean, stdv, uni, out);
}